// round 3
// baseline (speedup 1.0000x reference)
#include <cuda_runtime.h>

#define N_NODES 50000
#define N_PAIRS 625000
#define FDIM    128

// ---------------- scratch (no allocations allowed) ----------------
__device__ float g_v[(long)N_NODES * FDIM];   // x @ W   (25.6 MB)
__device__ int   g_cnt[N_NODES];              // histogram / fill cursors
__device__ int   g_off[N_NODES + 1];          // CSR offsets
__device__ int   g_order[N_PAIRS];            // pair ids sorted by idx_i

// ---------------- CSR construction ----------------
__global__ void k_zero_cnt() {
    int i = blockIdx.x * blockDim.x + threadIdx.x;
    if (i < N_NODES) g_cnt[i] = 0;
}

__global__ void k_hist(const int* __restrict__ idx_i) {
    int p = blockIdx.x * blockDim.x + threadIdx.x;
    if (p < N_PAIRS) atomicAdd(&g_cnt[idx_i[p]], 1);
}

// single block, 1024 threads: exclusive scan of g_cnt -> g_off, reset g_cnt
__global__ void k_scan() {
    __shared__ int ssum[1024];
    const int t  = threadIdx.x;
    const int CH = (N_NODES + 1023) / 1024;          // 49
    const int lo = t * CH;
    const int hi = min(lo + CH, N_NODES);

    int s = 0;
    for (int n = lo; n < hi; n++) s += g_cnt[n];
    ssum[t] = s;
    __syncthreads();

    // Hillis-Steele inclusive scan over 1024 partials
    for (int d = 1; d < 1024; d <<= 1) {
        int v = ssum[t];
        int u = (t >= d) ? ssum[t - d] : 0;
        __syncthreads();
        ssum[t] = v + u;
        __syncthreads();
    }

    int run = (t > 0) ? ssum[t - 1] : 0;             // exclusive base
    for (int n = lo; n < hi; n++) {
        int c = g_cnt[n];
        g_off[n] = run;
        run += c;
        g_cnt[n] = 0;                                 // reset for fill cursors
    }
    if (t == 1023) g_off[N_NODES] = ssum[1023];
}

__global__ void k_fill(const int* __restrict__ idx_i) {
    int p = blockIdx.x * blockDim.x + threadIdx.x;
    if (p < N_PAIRS) {
        int i = idx_i[p];
        int s = atomicAdd(&g_cnt[i], 1);
        g_order[g_off[i] + s] = p;
    }
}

// ---------------- GEMM: g_v = x @ W ----------------
// 128x128 output tile per block, 256 threads, 8x8 per-thread microtile, BK=32
__global__ __launch_bounds__(256) void k_gemm(const float* __restrict__ x,
                                              const float* __restrict__ W) {
    __shared__ float xs[128][33];     // padded: conflict-free column reads
    __shared__ float ws[32 * 128];

    const int tid  = threadIdx.x;
    const int tx   = tid & 15;        // 0..15 -> 8 output cols each
    const int ty   = tid >> 4;        // 0..15 -> 8 output rows each
    const int row0 = blockIdx.x * 128;

    float acc[8][8];
#pragma unroll
    for (int i = 0; i < 8; i++)
#pragma unroll
        for (int j = 0; j < 8; j++) acc[i][j] = 0.f;

    for (int kb = 0; kb < FDIM; kb += 32) {
        // W chunk [kb..kb+32) x [0..128): 4096 contiguous floats
        const float4* wsrc = (const float4*)(W + kb * FDIM);
        float4* wdst = (float4*)ws;
#pragma unroll
        for (int q = 0; q < 4; q++) wdst[tid + q * 256] = wsrc[tid + q * 256];

        // x tile: 128 rows x 32 k (1024 float4 loads)
#pragma unroll
        for (int q = 0; q < 4; q++) {
            int lin = tid + q * 256;          // 0..1023
            int r = lin >> 3;                 // row within tile
            int g = lin & 7;                  // float4 group within 32 floats
            float4 val = make_float4(0.f, 0.f, 0.f, 0.f);
            int row = row0 + r;
            if (row < N_NODES)
                val = *(const float4*)(x + (long)row * FDIM + kb + g * 4);
            xs[r][g * 4 + 0] = val.x;
            xs[r][g * 4 + 1] = val.y;
            xs[r][g * 4 + 2] = val.z;
            xs[r][g * 4 + 3] = val.w;
        }
        __syncthreads();

#pragma unroll
        for (int k = 0; k < 32; k++) {
            float a[8];
#pragma unroll
            for (int i = 0; i < 8; i++) a[i] = xs[ty * 8 + i][k];
            float4 b0 = *(const float4*)&ws[k * 128 + tx * 8];
            float4 b1 = *(const float4*)&ws[k * 128 + tx * 8 + 4];
#pragma unroll
            for (int i = 0; i < 8; i++) {
                acc[i][0] += a[i] * b0.x;
                acc[i][1] += a[i] * b0.y;
                acc[i][2] += a[i] * b0.z;
                acc[i][3] += a[i] * b0.w;
                acc[i][4] += a[i] * b1.x;
                acc[i][5] += a[i] * b1.y;
                acc[i][6] += a[i] * b1.z;
                acc[i][7] += a[i] * b1.w;
            }
        }
        __syncthreads();
    }

#pragma unroll
    for (int i = 0; i < 8; i++) {
        int row = row0 + ty * 8 + i;
        if (row < N_NODES) {
            float4 o0 = make_float4(acc[i][0], acc[i][1], acc[i][2], acc[i][3]);
            float4 o1 = make_float4(acc[i][4], acc[i][5], acc[i][6], acc[i][7]);
            float4* dst = (float4*)(g_v + (long)row * FDIM + tx * 8);
            dst[0] = o0;
            dst[1] = o1;
        }
    }
}

// ---------------- aggregation: one warp per output node ----------------
__global__ __launch_bounds__(256) void k_agg(const int* __restrict__ idx_j,
                                             const float* __restrict__ alpha,
                                             float* __restrict__ out) {
    const int wid  = (blockIdx.x * blockDim.x + threadIdx.x) >> 5;
    const int lane = threadIdx.x & 31;
    if (wid >= N_NODES) return;

    const int start = g_off[wid];
    const int end   = g_off[wid + 1];

    float4 acc = make_float4(0.f, 0.f, 0.f, 0.f);
    const float4* v4 = (const float4*)g_v;

    for (int base = start; base < end; base += 32) {
        int  k2 = base + lane;
        int  j  = 0;
        float a = 0.f;
        if (k2 < end) {
            int p = g_order[k2];
            j = idx_j[p];
            a = alpha[p];
        }
        const int m = min(32, end - base);
        for (int t = 0; t < m; t++) {
            int   jj = __shfl_sync(0xffffffffu, j, t);
            float aa = __shfl_sync(0xffffffffu, a, t);
            float4 vv = v4[(long)jj * 32 + lane];
            acc.x += aa * vv.x;
            acc.y += aa * vv.y;
            acc.z += aa * vv.z;
            acc.w += aa * vv.w;
        }
    }
    // every node writes (d_out is poisoned, degree-0 nodes must be zero)
    ((float4*)out)[(long)wid * 32 + lane] = acc;
}

// ---------------- launch ----------------
extern "C" void kernel_launch(void* const* d_in, const int* in_sizes, int n_in,
                              void* d_out, int out_size) {
    const float* x     = (const float*)d_in[0];
    const float* alpha = (const float*)d_in[1];
    const int*   idx_i = (const int*)d_in[2];
    const int*   idx_j = (const int*)d_in[3];
    const float* W     = (const float*)d_in[4];
    float*       out   = (float*)d_out;

    k_zero_cnt<<<(N_NODES + 255) / 256, 256>>>();
    k_hist<<<(N_PAIRS + 255) / 256, 256>>>(idx_i);
    k_scan<<<1, 1024>>>();
    k_fill<<<(N_PAIRS + 255) / 256, 256>>>(idx_i);
    k_gemm<<<(N_NODES + 127) / 128, 256>>>(x, W);
    k_agg<<<(N_NODES * 32 + 255) / 256, 256>>>(idx_j, alpha, out);
}

// round 4
// speedup vs baseline: 1.1430x; 1.1430x over previous
#include <cuda_runtime.h>

#define N_NODES 50000
#define N_PAIRS 625000
#define FDIM    128

typedef unsigned long long ull;

// ---------------- scratch (no allocations allowed) ----------------
__device__ float g_v[(long)N_NODES * FDIM];   // x @ W   (25.6 MB)
__device__ int   g_cnt[N_NODES];              // histogram / fill cursors
__device__ int   g_off[N_NODES + 1];          // CSR offsets
__device__ ull   g_ja[N_PAIRS];               // packed (alpha_bits<<32 | idx_j) in CSR order

// ---------------- f32x2 helpers ----------------
__device__ __forceinline__ ull pack_dup(float a) {
    ull r; asm("mov.b64 %0, {%1, %1};" : "=l"(r) : "f"(a)); return r;
}
__device__ __forceinline__ void ffma2(ull& d, ull a, ull b) {
    asm("fma.rn.f32x2 %0, %1, %2, %0;" : "+l"(d) : "l"(a), "l"(b));
}
__device__ __forceinline__ float2 unpack2(ull v) {
    float2 f; asm("mov.b64 {%0, %1}, %2;" : "=f"(f.x), "=f"(f.y) : "l"(v)); return f;
}

// ---------------- CSR construction ----------------
__global__ void k_zero_cnt() {
    int i = blockIdx.x * blockDim.x + threadIdx.x;
    if (i < N_NODES) g_cnt[i] = 0;
}

__global__ void k_hist(const int* __restrict__ idx_i) {
    int p = blockIdx.x * blockDim.x + threadIdx.x;
    if (p < N_PAIRS) atomicAdd(&g_cnt[idx_i[p]], 1);
}

// single block, 1024 threads: exclusive scan of g_cnt -> g_off, reset g_cnt
__global__ void k_scan() {
    __shared__ int ssum[1024];
    const int t  = threadIdx.x;
    const int CH = (N_NODES + 1023) / 1024;          // 49
    const int lo = t * CH;
    const int hi = min(lo + CH, N_NODES);

    int s = 0;
    for (int n = lo; n < hi; n++) s += g_cnt[n];
    ssum[t] = s;
    __syncthreads();

    for (int d = 1; d < 1024; d <<= 1) {
        int v = ssum[t];
        int u = (t >= d) ? ssum[t - d] : 0;
        __syncthreads();
        ssum[t] = v + u;
        __syncthreads();
    }

    int run = (t > 0) ? ssum[t - 1] : 0;             // exclusive base
    for (int n = lo; n < hi; n++) {
        int c = g_cnt[n];
        g_off[n] = run;
        run += c;
        g_cnt[n] = 0;                                 // reset for fill cursors
    }
    if (t == 1023) g_off[N_NODES] = ssum[1023];
}

// fill packed (alpha, j) records directly in CSR order
__global__ void k_fill(const int* __restrict__ idx_i,
                       const int* __restrict__ idx_j,
                       const float* __restrict__ alpha) {
    int p = blockIdx.x * blockDim.x + threadIdx.x;
    if (p < N_PAIRS) {
        int i = idx_i[p];
        int s = atomicAdd(&g_cnt[i], 1);
        ull rec = ((ull)__float_as_uint(alpha[p]) << 32) | (unsigned int)idx_j[p];
        g_ja[g_off[i] + s] = rec;
    }
}

// ---------------- GEMM: g_v = x @ W  (f32x2 packed FFMA) ----------------
// 128x128 output tile per block, 256 threads, 8x8 per-thread microtile, BK=32
__global__ __launch_bounds__(256) void k_gemm(const float* __restrict__ x,
                                              const float* __restrict__ W) {
    __shared__ float xs[128][33];     // padded: conflict-free column reads
    __shared__ float ws[32 * 128];

    const int tid  = threadIdx.x;
    const int tx   = tid & 15;        // 0..15 -> 8 output cols each
    const int ty   = tid >> 4;        // 0..15 -> 8 output rows each
    const int row0 = blockIdx.x * 128;

    ull acc2[8][4];                   // 8 rows x 4 column-pairs (f32x2)
#pragma unroll
    for (int i = 0; i < 8; i++)
#pragma unroll
        for (int j = 0; j < 4; j++) acc2[i][j] = 0ull;

    for (int kb = 0; kb < FDIM; kb += 32) {
        // W chunk [kb..kb+32) x [0..128): 4096 contiguous floats
        const float4* wsrc = (const float4*)(W + kb * FDIM);
        float4* wdst = (float4*)ws;
#pragma unroll
        for (int q = 0; q < 4; q++) wdst[tid + q * 256] = wsrc[tid + q * 256];

        // x tile: 128 rows x 32 k (1024 float4 loads)
#pragma unroll
        for (int q = 0; q < 4; q++) {
            int lin = tid + q * 256;          // 0..1023
            int r = lin >> 3;                 // row within tile
            int g = lin & 7;                  // float4 group within 32 floats
            float4 val = make_float4(0.f, 0.f, 0.f, 0.f);
            int row = row0 + r;
            if (row < N_NODES)
                val = *(const float4*)(x + (long)row * FDIM + kb + g * 4);
            xs[r][g * 4 + 0] = val.x;
            xs[r][g * 4 + 1] = val.y;
            xs[r][g * 4 + 2] = val.z;
            xs[r][g * 4 + 3] = val.w;
        }
        __syncthreads();

#pragma unroll
        for (int k = 0; k < 32; k++) {
            ull av[8];
#pragma unroll
            for (int i = 0; i < 8; i++) av[i] = pack_dup(xs[ty * 8 + i][k]);
            const ull* wrow = (const ull*)&ws[k * 128 + tx * 8];
            ull b0 = wrow[0], b1 = wrow[1], b2 = wrow[2], b3 = wrow[3];
#pragma unroll
            for (int i = 0; i < 8; i++) {
                ffma2(acc2[i][0], av[i], b0);
                ffma2(acc2[i][1], av[i], b1);
                ffma2(acc2[i][2], av[i], b2);
                ffma2(acc2[i][3], av[i], b3);
            }
        }
        __syncthreads();
    }

#pragma unroll
    for (int i = 0; i < 8; i++) {
        int row = row0 + ty * 8 + i;
        if (row < N_NODES) {
            float2 p0 = unpack2(acc2[i][0]);
            float2 p1 = unpack2(acc2[i][1]);
            float2 p2 = unpack2(acc2[i][2]);
            float2 p3 = unpack2(acc2[i][3]);
            float4* dst = (float4*)(g_v + (long)row * FDIM + tx * 8);
            dst[0] = make_float4(p0.x, p0.y, p1.x, p1.y);
            dst[1] = make_float4(p2.x, p2.y, p3.x, p3.y);
        }
    }
}

// ---------------- aggregation: one warp per output node ----------------
__global__ __launch_bounds__(256) void k_agg(float* __restrict__ out) {
    const int wid  = (blockIdx.x * blockDim.x + threadIdx.x) >> 5;
    const int lane = threadIdx.x & 31;
    if (wid >= N_NODES) return;

    const int start = g_off[wid];
    const int end   = g_off[wid + 1];

    float4 acc0 = make_float4(0.f, 0.f, 0.f, 0.f);
    float4 acc1 = make_float4(0.f, 0.f, 0.f, 0.f);
    const float4* v4 = (const float4*)g_v;

    for (int base = start; base < end; base += 32) {
        int k2 = base + lane;
        ull ja = (k2 < end) ? g_ja[k2] : 0ull;
        const int m = min(32, end - base);
        int t = 0;
        for (; t + 1 < m; t += 2) {
            ull p0 = __shfl_sync(0xffffffffu, ja, t);
            ull p1 = __shfl_sync(0xffffffffu, ja, t + 1);
            int   j0 = (int)(unsigned int)p0;
            int   j1 = (int)(unsigned int)p1;
            float a0 = __uint_as_float((unsigned int)(p0 >> 32));
            float a1 = __uint_as_float((unsigned int)(p1 >> 32));
            float4 v0 = v4[(long)j0 * 32 + lane];
            float4 v1 = v4[(long)j1 * 32 + lane];
            acc0.x += a0 * v0.x; acc0.y += a0 * v0.y;
            acc0.z += a0 * v0.z; acc0.w += a0 * v0.w;
            acc1.x += a1 * v1.x; acc1.y += a1 * v1.y;
            acc1.z += a1 * v1.z; acc1.w += a1 * v1.w;
        }
        if (t < m) {
            ull p0 = __shfl_sync(0xffffffffu, ja, t);
            int   j0 = (int)(unsigned int)p0;
            float a0 = __uint_as_float((unsigned int)(p0 >> 32));
            float4 v0 = v4[(long)j0 * 32 + lane];
            acc0.x += a0 * v0.x; acc0.y += a0 * v0.y;
            acc0.z += a0 * v0.z; acc0.w += a0 * v0.w;
        }
    }
    // every node writes (d_out is poisoned, degree-0 nodes must be zero)
    float4 r = make_float4(acc0.x + acc1.x, acc0.y + acc1.y,
                           acc0.z + acc1.z, acc0.w + acc1.w);
    ((float4*)out)[(long)wid * 32 + lane] = r;
}

// ---------------- launch (fork-join: GEMM || CSR build) ----------------
extern "C" void kernel_launch(void* const* d_in, const int* in_sizes, int n_in,
                              void* d_out, int out_size) {
    const float* x     = (const float*)d_in[0];
    const float* alpha = (const float*)d_in[1];
    const int*   idx_i = (const int*)d_in[2];
    const int*   idx_j = (const int*)d_in[3];
    const float* W     = (const float*)d_in[4];
    float*       out   = (float*)d_out;

    static cudaStream_t s2 = nullptr;
    static cudaEvent_t  e1 = nullptr, e2 = nullptr;
    if (s2 == nullptr) {
        cudaStreamCreateWithFlags(&s2, cudaStreamNonBlocking);
        cudaEventCreateWithFlags(&e1, cudaEventDisableTiming);
        cudaEventCreateWithFlags(&e2, cudaEventDisableTiming);
    }

    // fork: GEMM on s2, CSR build on the main (capture) stream
    cudaEventRecord(e1, 0);
    cudaStreamWaitEvent(s2, e1, 0);
    k_gemm<<<(N_NODES + 127) / 128, 256, 0, s2>>>(x, W);
    cudaEventRecord(e2, s2);

    k_zero_cnt<<<(N_NODES + 255) / 256, 256>>>();
    k_hist<<<(N_PAIRS + 255) / 256, 256>>>(idx_i);
    k_scan<<<1, 1024>>>();
    k_fill<<<(N_PAIRS + 255) / 256, 256>>>(idx_i, idx_j, alpha);

    // join, then aggregate
    cudaStreamWaitEvent(0, e2, 0);
    k_agg<<<(N_NODES * 32 + 255) / 256, 256>>>(out);
}